// round 13
// baseline (speedup 1.0000x reference)
#include <cuda_runtime.h>
#include <cstdint>

// Log-signature depth 3, d=8, L=256, B=2048.
// R12: 8-lane groups — lane owns i = lane&7, ALL (j,k) for that i:
//   S2[i,:] = 4 f32x2 regs (packed along j), S3[i,:,:] = 32 f32x2 regs
//   (packed along j: reg = (S3[2p,k],S3[2p+1,k])).
// One warp = one batch (4 chunks of 64 steps, lanes 8c..8c+7 = chunk c).
// Per step: 2 LDS.128 (plain dx pairs, reused for BOTH the j side of m and
// via 12 movs the duplicated k side), 1 LDS.32 (dx_i). m comes out of
// fma2 already packed along j -> feeds the 32 S3 fma2 directly (no
// unpack/repack on the critical chain).
// Chen combine is intra-warp (syncwarp only); sig slots alias the dx smem.
// grid=2048 1-warp blocks, launch_bounds(32,14) -> ~14 blocks/SM, 1 wave.

#define BATCH   2048
#define LPATH   256
#define DCH     8
#define OUT_PB  584
#define TPB     32
#define NCHUNK  4
#define CSTEPS  64
#define SIGSZ   656            // 8 S1 + 72 S2(8x9) + 576 S3(64x9)
#define SMEMF   2052           // dx 2048 + pad; sig 3*656=1968 + pub 72 alias

using u64 = unsigned long long;

__device__ __forceinline__ u64 pack2(float lo, float hi) {
    u64 r; asm("mov.b64 %0, {%1, %2};" : "=l"(r) : "f"(lo), "f"(hi)); return r;
}
__device__ __forceinline__ void unpack2(u64 v, float& lo, float& hi) {
    asm("mov.b64 {%0, %1}, %2;" : "=f"(lo), "=f"(hi) : "l"(v));
}
__device__ __forceinline__ u64 fma2(u64 a, u64 b, u64 c) {
    u64 d; asm("fma.rn.f32x2 %0, %1, %2, %3;" : "=l"(d) : "l"(a), "l"(b), "l"(c)); return d;
}

__global__ __launch_bounds__(TPB, 14)
void logsig_kernel(const float* __restrict__ x, float* __restrict__ out)
{
    __shared__ __align__(16) float smem[SMEMF];

    const int lane  = threadIdx.x;        // 0..31
    const int i     = lane & 7;           // owned i
    const int chunk = lane >> 3;          // 0..3
    const long b    = blockIdx.x;
    const int start = chunk * CSTEPS;

    const float4* xg = reinterpret_cast<const float4*>(x + (size_t)b * LPATH * DCH);

    // ---------------- phase 1: dx -> shared (dx[255] = 0 pad) ------------
#pragma unroll
    for (int k = 0; k < 16; ++k) {
        int e  = lane + 32 * k;           // 0..511 : (point, half)
        int t  = e >> 1;
        int h  = e & 1;
        int tn = (t < 255) ? t + 1 : 255;
        float4 cur = __ldg(xg + 2 * t  + h);
        float4 nxt = __ldg(xg + 2 * tn + h);
        float4 dv;
        dv.x = nxt.x - cur.x; dv.y = nxt.y - cur.y;
        dv.z = nxt.z - cur.z; dv.w = nxt.w - cur.w;
        *reinterpret_cast<float4*>(&smem[t * 8 + h * 4]) = dv;
    }
    __syncwarp();

    // ---------------- phase 2: 64-step packed scan ------------------------
    u64 S3p[4][8];                        // [jpair][k]
#pragma unroll
    for (int p = 0; p < 4; ++p)
#pragma unroll
        for (int k = 0; k < 8; ++k) S3p[p][k] = 0ull;
    u64 S2p[4] = {0ull, 0ull, 0ull, 0ull};
    float S1i = 0.0f;

    const float* dxp = &smem[start * 8];
    const longlong2* dv2 = reinterpret_cast<const longlong2*>(dxp);

#pragma unroll 2
    for (int t = 0; t < CSTEPS; ++t) {
        longlong2 va = dv2[2 * t];
        longlong2 vb = dv2[2 * t + 1];
        float dxi = dxp[t * 8 + i];

        u64 p01 = (u64)va.x, p23 = (u64)va.y;   // plain pairs (dx0,dx1)..
        u64 p45 = (u64)vb.x, p67 = (u64)vb.y;

        // duplicated k-side pairs (off the critical chain)
        float e0, e1, e2, e3, e4, e5, e6, e7;
        unpack2(p01, e0, e1); unpack2(p23, e2, e3);
        unpack2(p45, e4, e5); unpack2(p67, e6, e7);
        u64 D[8];
        D[0] = pack2(e0, e0); D[1] = pack2(e1, e1);
        D[2] = pack2(e2, e2); D[3] = pack2(e3, e3);
        D[4] = pack2(e4, e4); D[5] = pack2(e5, e5);
        D[6] = pack2(e6, e6); D[7] = pack2(e7, e7);

        float av = fmaf(dxi, 1.0f / 6.0f, 0.5f * S1i);   // old S1i
        float bv = fmaf(dxi, 0.5f, S1i);
        S1i += dxi;
        u64 a2 = pack2(av, av);
        u64 b2 = pack2(bv, bv);

        u64 m0 = fma2(a2, p01, S2p[0]);                  // packed (m_{2p},m_{2p+1})
        u64 m1 = fma2(a2, p23, S2p[1]);
        u64 m2 = fma2(a2, p45, S2p[2]);
        u64 m3 = fma2(a2, p67, S2p[3]);
        S2p[0] = fma2(b2, p01, S2p[0]);
        S2p[1] = fma2(b2, p23, S2p[1]);
        S2p[2] = fma2(b2, p45, S2p[2]);
        S2p[3] = fma2(b2, p67, S2p[3]);

#pragma unroll
        for (int k = 0; k < 8; ++k) {
            S3p[0][k] = fma2(m0, D[k], S3p[0][k]);
            S3p[1][k] = fma2(m1, D[k], S3p[1][k]);
            S3p[2][k] = fma2(m2, D[k], S3p[2][k]);
            S3p[3][k] = fma2(m3, D[k], S3p[3][k]);
        }
    }

    // ---- unpack scan state to scalars ----
    float S3f[8][8];                       // [j][k] for owned i
#pragma unroll
    for (int p = 0; p < 4; ++p)
#pragma unroll
        for (int k = 0; k < 8; ++k)
            unpack2(S3p[p][k], S3f[2 * p][k], S3f[2 * p + 1][k]);
    float S2f[8];
#pragma unroll
    for (int p = 0; p < 4; ++p)
        unpack2(S2p[p], S2f[2 * p], S2f[2 * p + 1]);

    // S1 via telescoped endpoints (GMEM, L1/L2-hot)
    float S1f[8];
    {
        int pend = (chunk == 3) ? 255 : (start + CSTEPS);
        float4 e0 = __ldg(xg + 2 * pend);
        float4 e1 = __ldg(xg + 2 * pend + 1);
        float4 s0 = __ldg(xg + 2 * start);
        float4 s1 = __ldg(xg + 2 * start + 1);
        S1f[0] = e0.x - s0.x; S1f[1] = e0.y - s0.y;
        S1f[2] = e0.z - s0.z; S1f[3] = e0.w - s0.w;
        S1f[4] = e1.x - s1.x; S1f[5] = e1.y - s1.y;
        S1f[6] = e1.z - s1.z; S1f[7] = e1.w - s1.w;
    }

    // ---------------- Chen tree-combine, intra-warp (smem aliases dx) ----
    auto store_sig = [&](float* p) {
        if (i == 0) {
#pragma unroll
            for (int k = 0; k < 8; ++k) p[k] = S1f[k];
        }
#pragma unroll
        for (int j = 0; j < 8; ++j)
            p[8 + i * 9 + j] = S2f[j];
#pragma unroll
        for (int j = 0; j < 8; ++j)
#pragma unroll
            for (int k = 0; k < 8; ++k)
                p[80 + (i * 8 + j) * 9 + k] = S3f[j][k];
    };

    auto combine = [&](const float* p) {   // regs = earlier a, p = later b
        float S1b[8];
#pragma unroll
        for (int k = 0; k < 8; ++k) S1b[k] = p[k];
#pragma unroll
        for (int j = 0; j < 8; ++j) {
            const float* s2row = p + 8 + j * 9;              // S2b[j,:]
            const float* s3row = p + 80 + (i * 8 + j) * 9;   // S3b[i,j,:]
#pragma unroll
            for (int k = 0; k < 8; ++k)
                S3f[j][k] += S2f[j] * S1b[k] + S1i * s2row[k] + s3row[k];
            S2f[j] += S1i * S1b[j] + p[8 + i * 9 + j];
        }
#pragma unroll
        for (int k = 0; k < 8; ++k) S1f[k] += S1b[k];
        S1i += S1b[i];
    };

    __syncwarp();                          // scan's dx reads done
    if (chunk == 1) store_sig(&smem[0]);
    if (chunk == 3) store_sig(&smem[SIGSZ]);
    __syncwarp();
    if (chunk == 0) {
        combine(&smem[0]);
    } else if (chunk == 2) {
        combine(&smem[SIGSZ]);
        store_sig(&smem[2 * SIGSZ]);
    }
    __syncwarp();
    if (chunk != 0) return;

    combine(&smem[2 * SIGSZ]);

    // ---------------- log projection + writeback -------------------------
    float* pub = &smem[3 * SIGSZ];         // 72 floats, stride-9 S2 rows
#pragma unroll
    for (int j = 0; j < 8; ++j)
        pub[i * 9 + j] = S2f[j];
    __syncwarp(0x000000FFu);

    float* ob = out + (size_t)b * OUT_PB;

    // l1
    if (lane == 0) {
        *reinterpret_cast<float4*>(ob)     = make_float4(S1f[0], S1f[1], S1f[2], S1f[3]);
        *reinterpret_cast<float4*>(ob + 4) = make_float4(S1f[4], S1f[5], S1f[6], S1f[7]);
    }

    // l2 = S2 - 0.5 S1 x S1  (lane i writes row i: 8 floats)
    {
        float4 lo, hi;
        float* lv = &lo.x; float* hv = &hi.x;
#pragma unroll
        for (int j = 0; j < 8; ++j) {
            float v = S2f[j] - 0.5f * S1i * S1f[j];
            if (j < 4) lv[j] = v; else hv[j - 4] = v;
        }
        float* dst = ob + 8 + 8 * i;
        *reinterpret_cast<float4*>(dst)     = lo;
        *reinterpret_cast<float4*>(dst + 4) = hi;
    }

    // l3 = S3 - 0.5 (S1_i S2[j,k] + S2[i,j] S1_k) + (1/3) S1_i S1_j S1_k
#pragma unroll
    for (int j = 0; j < 8; ++j) {
        float S2ij = S2f[j];
        float tij  = (1.0f / 3.0f) * S1i * S1f[j];
        const float* row = pub + j * 9;       // combined S2[j,:]
        float4 lo, hi;
        float* lv = &lo.x; float* hv = &hi.x;
#pragma unroll
        for (int k = 0; k < 8; ++k) {
            float val = S3f[j][k]
                      - 0.5f * (S1i * row[k] + S2ij * S1f[k])
                      + tij * S1f[k];
            if (k < 4) lv[k] = val; else hv[k - 4] = val;
        }
        float* dst = ob + 72 + i * 64 + j * 8;
        *reinterpret_cast<float4*>(dst)     = lo;
        *reinterpret_cast<float4*>(dst + 4) = hi;
    }
}

extern "C" void kernel_launch(void* const* d_in, const int* in_sizes, int n_in,
                              void* d_out, int out_size)
{
    const float* x = (const float*)d_in[0];
    float* out = (float*)d_out;
    (void)in_sizes; (void)n_in; (void)out_size;

    logsig_kernel<<<BATCH, TPB>>>(x, out);   // 2048 one-warp blocks
}

// round 15
// speedup vs baseline: 1.0707x; 1.0707x over previous
#include <cuda_runtime.h>
#include <cstdint>

// Log-signature depth 3, d=8, L=256, B=2048.
// R13 = R11 (smem-staged dx, packed f32x2 scan, 3 chunks of 85 steps,
// fine-grain 96-thread blocks, Chen combine in aliased smem) with the
// per-step dj LDS.128 replaced by register SELs from the already-loaded
// dx pairs: LDS wavefronts/step 13 -> 9 and the m-chain producer drops
// from a 29-cyc LDS to a 4-cyc SEL.

#define BATCH   2048
#define LPATH   256
#define DCH     8
#define OUT_PB  584
#define TPB     96             // 6 groups = 2 batches x 3 chunks
#define BPB     2
#define NCHUNK  3
#define CSTEPS  85             // 255 / 3
#define SIGSZ   656            // 8 + 8x9 (S2) + 64x9 (S3)
#define DXS     2052           // floats per batch dx region (8*256 + 4 pad)
#define SMEMF   4104           // 2*DXS; >= 6*SIGSZ = 3936 (sig aliases dx)

using u64 = unsigned long long;

__device__ __forceinline__ u64 pack2(float lo, float hi) {
    u64 r; asm("mov.b64 %0, {%1, %2};" : "=l"(r) : "f"(lo), "f"(hi)); return r;
}
__device__ __forceinline__ void unpack2(u64 v, float& lo, float& hi) {
    asm("mov.b64 {%0, %1}, %2;" : "=f"(lo), "=f"(hi) : "l"(v));
}
__device__ __forceinline__ u64 fma2(u64 a, u64 b, u64 c) {
    u64 d; asm("fma.rn.f32x2 %0, %1, %2, %3;" : "=l"(d) : "l"(a), "l"(b), "l"(c)); return d;
}

__global__ __launch_bounds__(TPB, 8)
void logsig_kernel(const float* __restrict__ x, float* __restrict__ out)
{
    __shared__ __align__(16) float smem[SMEMF];

    const int tid  = threadIdx.x;
    const int lane = tid & 31;
    const int s    = lane & 15;
    const int i    = s >> 1;
    const bool hib = (s & 1) != 0;
    const int jb   = hib ? 4 : 0;
    const unsigned gmask = 0xFFFFu << (lane & 16);

    const int gid   = tid >> 4;        // 0..5
    const int bL    = gid / NCHUNK;    // batch within block (0..1)
    const int chunk = gid - bL * NCHUNK;
    const long b = (long)blockIdx.x * BPB + bL;
    const int start = chunk * CSTEPS;

    // ---------------- phase 1: dx -> shared ----------------
    {
        const float4* xg = reinterpret_cast<const float4*>(
            x + (size_t)blockIdx.x * BPB * LPATH * DCH);
#pragma unroll
        for (int k = 0; k < 11; ++k) {
            int e = tid + TPB * k;          // (batch, point, half) in float4 units
            if (e < BPB * 512) {
                int bb = e >> 9;
                int r  = e & 511;
                int t  = r >> 1;
                int h  = r & 1;
                int tn = (t < 255) ? t + 1 : 255;   // dx[255] never read
                const float4* xb4 = xg + bb * 512;
                float4 cur = __ldg(xb4 + 2 * t  + h);
                float4 nxt = __ldg(xb4 + 2 * tn + h);
                float4 dv;
                dv.x = nxt.x - cur.x; dv.y = nxt.y - cur.y;
                dv.z = nxt.z - cur.z; dv.w = nxt.w - cur.w;
                *reinterpret_cast<float4*>(&smem[bb * DXS + t * 8 + h * 4]) = dv;
            }
        }
    }
    __syncthreads();

    // ---------------- phase 2: 85-step packed scan from smem -------------
    u64 S3p[4][4];
#pragma unroll
    for (int q = 0; q < 4; ++q)
#pragma unroll
        for (int kp = 0; kp < 4; ++kp) S3p[q][kp] = 0ull;
    u64 S2p0 = 0ull, S2p1 = 0ull;
    float S1i = 0.0f;

    const float* dxp = &smem[bL * DXS + start * 8];
    const longlong2* dv2 = reinterpret_cast<const longlong2*>(dxp);

#pragma unroll 4
    for (int t = 0; t < CSTEPS; ++t) {
        longlong2 va = dv2[2 * t];
        longlong2 vb = dv2[2 * t + 1];
        float dxi = dxp[t * 8 + i];

        u64 d0 = (u64)va.x, d1 = (u64)va.y, d2 = (u64)vb.x, d3 = (u64)vb.y;
        // dj pairs from registers (4-cyc SEL instead of a 29-cyc LDS.128)
        u64 dj01 = hib ? d2 : d0;
        u64 dj23 = hib ? d3 : d1;

        float av = fmaf(dxi, 1.0f / 6.0f, 0.5f * S1i);   // old S1i
        float bv = fmaf(dxi, 0.5f, S1i);
        S1i += dxi;
        u64 a2 = pack2(av, av);
        u64 b2 = pack2(bv, bv);

        u64 m01 = fma2(a2, dj01, S2p0);                  // old S2
        u64 m23 = fma2(a2, dj23, S2p1);
        S2p0 = fma2(b2, dj01, S2p0);
        S2p1 = fma2(b2, dj23, S2p1);

        float m0, m1, m2, m3;
        unpack2(m01, m0, m1); unpack2(m23, m2, m3);
        u64 M0 = pack2(m0, m0), M1 = pack2(m1, m1);
        u64 M2 = pack2(m2, m2), M3 = pack2(m3, m3);

        S3p[0][0] = fma2(M0, d0, S3p[0][0]);
        S3p[0][1] = fma2(M0, d1, S3p[0][1]);
        S3p[0][2] = fma2(M0, d2, S3p[0][2]);
        S3p[0][3] = fma2(M0, d3, S3p[0][3]);
        S3p[1][0] = fma2(M1, d0, S3p[1][0]);
        S3p[1][1] = fma2(M1, d1, S3p[1][1]);
        S3p[1][2] = fma2(M1, d2, S3p[1][2]);
        S3p[1][3] = fma2(M1, d3, S3p[1][3]);
        S3p[2][0] = fma2(M2, d0, S3p[2][0]);
        S3p[2][1] = fma2(M2, d1, S3p[2][1]);
        S3p[2][2] = fma2(M2, d2, S3p[2][2]);
        S3p[2][3] = fma2(M2, d3, S3p[2][3]);
        S3p[3][0] = fma2(M3, d0, S3p[3][0]);
        S3p[3][1] = fma2(M3, d1, S3p[3][1]);
        S3p[3][2] = fma2(M3, d2, S3p[3][2]);
        S3p[3][3] = fma2(M3, d3, S3p[3][3]);
    }

    // ---- unpack scan state; S1 via telescoped endpoints (GMEM, L2-hot) --
    float S3f[4][8];
#pragma unroll
    for (int q = 0; q < 4; ++q)
#pragma unroll
        for (int kp = 0; kp < 4; ++kp)
            unpack2(S3p[q][kp], S3f[q][2 * kp], S3f[q][2 * kp + 1]);
    float S2f[4];
    unpack2(S2p0, S2f[0], S2f[1]);
    unpack2(S2p1, S2f[2], S2f[3]);

    float S1f[8];
    {
        const float4* xg2 = reinterpret_cast<const float4*>(
            x + (size_t)b * LPATH * DCH);
        int pend = start + CSTEPS;        // 85 / 170 / 255 — always in range
        float4 e0 = __ldg(xg2 + 2 * pend);
        float4 e1 = __ldg(xg2 + 2 * pend + 1);
        float4 s0 = __ldg(xg2 + 2 * start);
        float4 s1 = __ldg(xg2 + 2 * start + 1);
        S1f[0] = e0.x - s0.x; S1f[1] = e0.y - s0.y;
        S1f[2] = e0.z - s0.z; S1f[3] = e0.w - s0.w;
        S1f[4] = e1.x - s1.x; S1f[5] = e1.y - s1.y;
        S1f[6] = e1.z - s1.z; S1f[7] = e1.w - s1.w;
    }

    // ---------------- Chen combine (smem aliased over dx) ----------------
    __syncthreads();                       // dx buffer dead from here on
    float (*sig)[SIGSZ] = reinterpret_cast<float (*)[SIGSZ]>(smem);

    auto store_sig = [&](float* p) {
        if (s == 0) {
#pragma unroll
            for (int k = 0; k < 8; ++k) p[k] = S1f[k];
        }
#pragma unroll
        for (int q = 0; q < 4; ++q)
            p[8 + i * 9 + jb + q] = S2f[q];
#pragma unroll
        for (int q = 0; q < 4; ++q)
#pragma unroll
            for (int k = 0; k < 8; ++k)
                p[80 + (i * 8 + jb + q) * 9 + k] = S3f[q][k];
    };

    auto combine = [&](const float* p) {   // regs = earlier part a, p = later part b
        float S1b[8];
#pragma unroll
        for (int k = 0; k < 8; ++k) S1b[k] = p[k];
#pragma unroll
        for (int q = 0; q < 4; ++q) {
            const float* s2row = p + 8 + (jb + q) * 9;            // S2b[j,:]
            const float* s3row = p + 80 + (i * 8 + jb + q) * 9;   // S3b[i,j,:]
#pragma unroll
            for (int k = 0; k < 8; ++k)
                S3f[q][k] += S2f[q] * S1b[k] + S1i * s2row[k] + s3row[k];
            float S1bj = hib ? S1b[4 + q] : S1b[q];
            S2f[q] += S1i * S1bj + p[8 + i * 9 + jb + q];
        }
#pragma unroll
        for (int k = 0; k < 8; ++k) S1f[k] += S1b[k];
        S1i += p[i];
    };

    if (chunk != 0) store_sig(&sig[bL * NCHUNK + chunk][0]);
    __syncthreads();
    if (chunk != 0) return;

    combine(&sig[bL * NCHUNK + 1][0]);
    combine(&sig[bL * NCHUNK + 2][0]);

    // ---------------- log projection + writeback ----------------
    float* p0 = &sig[bL * NCHUNK + 0][0];
#pragma unroll
    for (int q = 0; q < 4; ++q)
        p0[8 + i * 9 + jb + q] = S2f[q];   // publish full S2 for [j,k] reads
    __syncwarp(gmask);

    float* ob = out + (size_t)b * OUT_PB;

    // l1
    if (s == 0) {
        *reinterpret_cast<float4*>(ob)     = make_float4(S1f[0], S1f[1], S1f[2], S1f[3]);
        *reinterpret_cast<float4*>(ob + 4) = make_float4(S1f[4], S1f[5], S1f[6], S1f[7]);
    }

    // l2 = S2 - 0.5 S1 x S1
    {
        float4 v; float* vv = &v.x;
#pragma unroll
        for (int q = 0; q < 4; ++q) {
            float S1j = hib ? S1f[4 + q] : S1f[q];
            vv[q] = S2f[q] - 0.5f * S1i * S1j;
        }
        *reinterpret_cast<float4*>(ob + 8 + 4 * s) = v;
    }

    // l3 = S3 - 0.5 (S1_i S2[j,k] + S2[i,j] S1_k) + (1/3) S1_i S1_j S1_k
#pragma unroll
    for (int q = 0; q < 4; ++q) {
        float S1j  = hib ? S1f[4 + q] : S1f[q];
        float S2ij = S2f[q];
        float tij  = (1.0f / 3.0f) * S1i * S1j;
        const float* row = p0 + 8 + (jb + q) * 9;    // S2[j,:]
        float4 lo, hi4;
        float* lv = &lo.x; float* hv = &hi4.x;
#pragma unroll
        for (int k = 0; k < 8; ++k) {
            float val = S3f[q][k]
                      - 0.5f * (S1i * row[k] + S2ij * S1f[k])
                      + tij * S1f[k];
            if (k < 4) lv[k] = val; else hv[k - 4] = val;
        }
        float* dst = ob + 72 + 32 * s + 8 * q;
        *reinterpret_cast<float4*>(dst)     = lo;
        *reinterpret_cast<float4*>(dst + 4) = hi4;
    }
}

extern "C" void kernel_launch(void* const* d_in, const int* in_sizes, int n_in,
                              void* d_out, int out_size)
{
    const float* x = (const float*)d_in[0];
    float* out = (float*)d_out;
    (void)in_sizes; (void)n_in; (void)out_size;

    const int blocks = BATCH / BPB;   // 1024
    logsig_kernel<<<blocks, TPB>>>(x, out);
}